// round 12
// baseline (speedup 1.0000x reference)
#include <cuda_runtime.h>
#include <cuda_fp16.h>
#include <cstdint>

#define Bdim 8
#define Tdim 2048
#define Cdim 1024
#define Hdim 128
#define BT (Bdim*Tdim)

// Scratch (device globals, allocation-free).
__device__ __half g_xh[BT * Cdim];            // x in fp16
__device__ uint2  g_Wf[3 * 16 * 4 * 16 * 32]; // W fragment-packed fp16 (Wq pre-scaled)
__device__ __half g_Qh[BT * Hdim];            // Q fp16 (pre-scaled via Wf)
__device__ __half g_Kh[BT * Hdim];            // K fp16
__device__ __half g_Vp[BT * Hdim];            // V fp16, kv-paired: [t2][h][2]
__device__ float  g_Op[3 * BT * Hdim];        // unnormalized partial O per third
__device__ float  g_m[3 * BT];
__device__ float  g_l[3 * BT];

// ---------------------------------------------------------------------------
// Helpers
// ---------------------------------------------------------------------------
__device__ __forceinline__ uint32_t h2u(float a, float b) {
    __half2 h = __floats2half2_rn(a, b);
    return *(uint32_t*)&h;
}
__device__ __forceinline__ void mma_f16(float* d, const uint32_t* a,
                                        uint32_t b0, uint32_t b1) {
    asm volatile(
        "mma.sync.aligned.m16n8k16.row.col.f32.f16.f16.f32 "
        "{%0,%1,%2,%3}, {%4,%5,%6,%7}, {%8,%9}, {%0,%1,%2,%3};"
        : "+f"(d[0]), "+f"(d[1]), "+f"(d[2]), "+f"(d[3])
        : "r"(a[0]), "r"(a[1]), "r"(a[2]), "r"(a[3]), "r"(b0), "r"(b1));
}
__device__ __forceinline__ uint32_t s2u(const void* p) {
    return (uint32_t)__cvta_generic_to_shared(p);
}
__device__ __forceinline__ void cpa16(uint32_t dst, const void* src) {
    asm volatile("cp.async.cg.shared.global [%0], [%1], 16;" :: "r"(dst), "l"(src));
}
__device__ __forceinline__ void cpa_commit() {
    asm volatile("cp.async.commit_group;");
}
__device__ __forceinline__ void cpa_wait0() {
    asm volatile("cp.async.wait_group 0;");
}

// ---------------------------------------------------------------------------
// Prologue A: x -> fp16.
// ---------------------------------------------------------------------------
__global__ __launch_bounds__(256) void xh_kernel(const float* __restrict__ x)
{
    const size_t i = (size_t)blockIdx.x * 256 + threadIdx.x;  // 0..2097151
    const float4 v0 = ((const float4*)x)[2 * i];
    const float4 v1 = ((const float4*)x)[2 * i + 1];
    uint4 p;
    p.x = h2u(v0.x, v0.y); p.y = h2u(v0.z, v0.w);
    p.z = h2u(v1.x, v1.y); p.w = h2u(v1.z, v1.w);
    ((uint4*)g_xh)[i] = p;
}

// ---------------------------------------------------------------------------
// Prologue B: W -> fragment-packed fp16 (Wq pre-scaled by 1/sqrt(128)).
// ---------------------------------------------------------------------------
__global__ __launch_bounds__(256) void wf_kernel(
    const float* __restrict__ Wq, const float* __restrict__ Wk,
    const float* __restrict__ Wv)
{
    const int t = blockIdx.x * 256 + threadIdx.x;   // 0..98303
    const int lane = t & 31;
    const int nb = (t >> 5) & 15;
    const int ks = (t >> 9) & 3;
    const int kc = (t >> 11) & 15;
    const int o  = t >> 15;
    const int g = lane >> 2, tg = lane & 3;
    const float* W = (o == 0) ? Wq : (o == 1) ? Wk : Wv;
    const float sc = (o == 0) ? 0.08838834764831845f : 1.f;
    const int K0 = kc * 64 + ks * 16;
    const int n  = nb * 8 + g;
    uint2 r;
    r.x = h2u(W[(size_t)(K0 + 2*tg    ) * Hdim + n] * sc,
              W[(size_t)(K0 + 2*tg + 1) * Hdim + n] * sc);
    r.y = h2u(W[(size_t)(K0 + 2*tg + 8) * Hdim + n] * sc,
              W[(size_t)(K0 + 2*tg + 9) * Hdim + n] * sc);
    g_Wf[t] = r;
}

// ---------------------------------------------------------------------------
// Kernel 1: QKV projection, fp16 m16n8k16, cp.async double-buffered, k-chunk 64.
// grid = (BT/128, 3), block = 128. Outputs fp16 (V in kv-paired layout).
// ---------------------------------------------------------------------------
#define QKV_SMEM 69632

__global__ __launch_bounds__(128, 3) void qkv_kernel()
{
    extern __shared__ char qsm[];
    __half* Ah[2] = { (__half*)qsm, (__half*)(qsm + 18432) };
    uint2*  Bf[2] = { (uint2*)(qsm + 36864), (uint2*)(qsm + 53248) };

    const int m0 = blockIdx.x * 128;
    const int o  = blockIdx.y;
    const int tid  = threadIdx.x;
    const int wid  = tid >> 5;
    const int lane = tid & 31;
    const int g    = lane >> 2;
    const int tg   = lane & 3;

    const __half* Ag = g_xh + (size_t)m0 * Cdim;
    const uint2*  Bg = g_Wf + (size_t)o * 16 * 2048;

    {
        uint32_t au = s2u(Ah[0]), bu = s2u(Bf[0]);
        #pragma unroll
        for (int t = 0; t < 8; t++) {
            int idx = t * 128 + tid;
            int row = idx >> 3, c = idx & 7;
            cpa16(au + row * 144 + c * 16, Ag + (size_t)row * Cdim + c * 8);
            cpa16(bu + idx * 16, (const char*)Bg + idx * 16);
        }
        cpa_commit();
    }

    float oc[2][16][4];
    #pragma unroll
    for (int mb = 0; mb < 2; mb++)
        #pragma unroll
        for (int nb = 0; nb < 16; nb++)
            #pragma unroll
            for (int c = 0; c < 4; c++) oc[mb][nb][c] = 0.f;

    #pragma unroll 1
    for (int kc = 0; kc < 16; kc++) {
        cpa_wait0();
        __syncthreads();
        const int cur = kc & 1;
        if (kc + 1 < 16) {
            uint32_t au = s2u(Ah[cur ^ 1]), bu = s2u(Bf[cur ^ 1]);
            const __half* Agn = Ag + (kc + 1) * 64;
            const uint2*  Bgn = Bg + (kc + 1) * 2048;
            #pragma unroll
            for (int t = 0; t < 8; t++) {
                int idx = t * 128 + tid;
                int row = idx >> 3, c = idx & 7;
                cpa16(au + row * 144 + c * 16, Agn + (size_t)row * Cdim + c * 8);
                cpa16(bu + idx * 16, (const char*)Bgn + idx * 16);
            }
            cpa_commit();
        }

        const __half* A = Ah[cur];
        const uint2*  B = Bf[cur];
        const int r0 = wid * 32 + g;
        #pragma unroll
        for (int ks = 0; ks < 4; ks++) {
            const int kcol = ks * 16 + 2 * tg;
            uint32_t a0[4], a1[4];
            a0[0] = *(const uint32_t*)&A[(r0     ) * 72 + kcol    ];
            a0[1] = *(const uint32_t*)&A[(r0 +  8) * 72 + kcol    ];
            a0[2] = *(const uint32_t*)&A[(r0     ) * 72 + kcol + 8];
            a0[3] = *(const uint32_t*)&A[(r0 +  8) * 72 + kcol + 8];
            a1[0] = *(const uint32_t*)&A[(r0 + 16) * 72 + kcol    ];
            a1[1] = *(const uint32_t*)&A[(r0 + 24) * 72 + kcol    ];
            a1[2] = *(const uint32_t*)&A[(r0 + 16) * 72 + kcol + 8];
            a1[3] = *(const uint32_t*)&A[(r0 + 24) * 72 + kcol + 8];
            #pragma unroll
            for (int nb = 0; nb < 16; nb++) {
                uint2 bb = B[(ks * 16 + nb) * 32 + lane];
                mma_f16(oc[0][nb], a0, bb.x, bb.y);
                mma_f16(oc[1][nb], a1, bb.x, bb.y);
            }
        }
    }

    if (o < 2) {
        __half* outp = (o == 0) ? g_Qh : g_Kh;
        #pragma unroll
        for (int mb = 0; mb < 2; mb++) {
            int r = m0 + wid * 32 + mb * 16 + g;
            #pragma unroll
            for (int nb = 0; nb < 16; nb++) {
                int col = nb * 8 + 2 * tg;
                *(uint32_t*)&outp[(size_t)(r    ) * Hdim + col] = h2u(oc[mb][nb][0], oc[mb][nb][1]);
                *(uint32_t*)&outp[(size_t)(r + 8) * Hdim + col] = h2u(oc[mb][nb][2], oc[mb][nb][3]);
            }
        }
    } else {
        __syncthreads();
        __half* Vt = (__half*)qsm;   // [128][136]
        #pragma unroll
        for (int mb = 0; mb < 2; mb++) {
            int lr = wid * 32 + mb * 16 + g;
            #pragma unroll
            for (int nb = 0; nb < 16; nb++) {
                int col = nb * 8 + 2 * tg;
                *(uint32_t*)&Vt[(lr    ) * 136 + col] = h2u(oc[mb][nb][0], oc[mb][nb][1]);
                *(uint32_t*)&Vt[(lr + 8) * 136 + col] = h2u(oc[mb][nb][2], oc[mb][nb][3]);
            }
        }
        __syncthreads();
        uint32_t* Vpo = (uint32_t*)g_Vp;
        #pragma unroll
        for (int q = 0; q < 64; q++) {
            int idx = q * 128 + tid;
            int t2l = idx >> 7, hh = idx & 127;
            __half lo = Vt[(2 * t2l    ) * 136 + hh];
            __half hi = Vt[(2 * t2l + 1) * 136 + hh];
            __half2 pk = __halves2half2(lo, hi);
            Vpo[(size_t)(m0 / 2 + t2l) * 128 + hh] = *(uint32_t*)&pk;
        }
    }
}

// ---------------------------------------------------------------------------
// Kernel 2: causal flash attention, fp16 m16n8k16, 3-way split-KV + q-pairing.
// grid (48, 8): blockIdx.x = pair*3 + third. Third t takes 32-wide kv tiles
// i ≡ t (mod 3); over the (p, 31-p) phase pair that's 22±1 uniform steps.
// 384 CTAs, 3 CTAs/SM (launch_bounds cap) -> single wave.
// block = 128 (4 warps). Q fragments via __ldg; K/V double-buffered cp.async;
// P register-resident. Smem: K[2][32][136] + Vp[2][16][272] halves = 34816 B.
// ---------------------------------------------------------------------------
#define ATTN_SMEM 34816

__global__ __launch_bounds__(128, 3) void attn_kernel()
{
    extern __shared__ __half hsm[];
    __half* Kb[2] = { hsm,        hsm + 4352 };   // [32][136] x2
    __half* Vb[2] = { hsm + 8704, hsm + 13056 };  // [16][272] x2

    const int p  = (int)blockIdx.x / 3;
    const int t3 = (int)blockIdx.x % 3;
    const int b  = blockIdx.y;
    const int tid  = threadIdx.x;
    const int wid  = tid >> 5;
    const int lane = tid & 31;
    const int g    = lane >> 2;
    const int tg   = lane & 3;
    const int r0q  = wid * 16 + g;

    const __half* Qg = g_Qh + (size_t)b * Tdim * Hdim;
    const __half* Kg = g_Kh + (size_t)b * Tdim * Hdim;
    const __half* Vg = g_Vp + (size_t)b * Tdim * Hdim;   // paired: t2*256 + 2h+j

    #pragma unroll 1
    for (int phase = 0; phase < 2; phase++) {
        const int qt = phase == 0 ? p : 31 - p;
        const int m0 = qt * 64;
        const int n_tiles = 2 * qt + 2;                   // 32-wide kv tiles
        const int cnt = (n_tiles > t3) ? (n_tiles - 1 - t3) / 3 + 1 : 0;

        __syncthreads();  // previous phase's smem fully consumed

        // Stage first tile (index t3).
        if (cnt > 0) {
            const int n0 = 32 * t3;
            uint32_t ku = s2u(Kb[0]), vu = s2u(Vb[0]);
            #pragma unroll
            for (int t = 0; t < 4; t++) {
                int idx = t * 128 + tid;
                int krow = idx >> 4, kcc = idx & 15;
                cpa16(ku + krow * 272 + kcc * 16,
                      Kg + (size_t)(n0 + krow) * Hdim + kcc * 8);
                int vrow = idx >> 5, vcc = idx & 31;
                cpa16(vu + vrow * 544 + vcc * 16,
                      Vg + ((size_t)(n0 / 2 + vrow) * 256 + vcc * 8));
            }
            cpa_commit();
        }

        // Q fragments straight from global.
        uint32_t qf[8][4];
        {
            const __half* Qr0 = Qg + (size_t)(m0 + r0q) * Hdim;
            const __half* Qr1 = Qr0 + 8 * Hdim;
            #pragma unroll
            for (int ks = 0; ks < 8; ks++) {
                const int kcol = ks * 16 + 2 * tg;
                qf[ks][0] = __ldg((const uint32_t*)(Qr0 + kcol    ));
                qf[ks][1] = __ldg((const uint32_t*)(Qr1 + kcol    ));
                qf[ks][2] = __ldg((const uint32_t*)(Qr0 + kcol + 8));
                qf[ks][3] = __ldg((const uint32_t*)(Qr1 + kcol + 8));
            }
        }

        float of[16][4];
        #pragma unroll
        for (int nb = 0; nb < 16; nb++)
            #pragma unroll
            for (int c = 0; c < 4; c++) of[nb][c] = 0.f;
        float mrow0 = -1e30f, mrow1 = -1e30f, lrow0 = 0.f, lrow1 = 0.f;

        #pragma unroll 1
        for (int j = 0; j < cnt; j++) {
            const int cur = j & 1;
            const int i = t3 + 3 * j;          // 32-wide tile index
            cpa_wait0();
            __syncthreads();

            if (j + 1 < cnt) {
                const int n0n = 32 * (i + 3);
                uint32_t ku = s2u(Kb[cur ^ 1]), vu = s2u(Vb[cur ^ 1]);
                #pragma unroll
                for (int t = 0; t < 4; t++) {
                    int idx = t * 128 + tid;
                    int krow = idx >> 4, kcc = idx & 15;
                    cpa16(ku + krow * 272 + kcc * 16,
                          Kg + (size_t)(n0n + krow) * Hdim + kcc * 8);
                    int vrow = idx >> 5, vcc = idx & 31;
                    cpa16(vu + vrow * 544 + vcc * 16,
                          Vg + ((size_t)(n0n / 2 + vrow) * 256 + vcc * 8));
                }
                cpa_commit();
            }

            const __half* Kc = Kb[cur];
            const __half* Vc = Vb[cur];
            const int n0 = 32 * i;

            // S = Q . K^T  (16 q-rows x 32 kv per warp)
            float sacc[4][4];
            #pragma unroll
            for (int nb = 0; nb < 4; nb++)
                #pragma unroll
                for (int c = 0; c < 4; c++) sacc[nb][c] = 0.f;

            #pragma unroll
            for (int ks = 0; ks < 8; ks++) {
                const int kcol = ks * 16 + 2 * tg;
                #pragma unroll
                for (int nb = 0; nb < 4; nb++) {
                    uint32_t b0 = *(const uint32_t*)&Kc[(nb * 8 + g) * 136 + kcol    ];
                    uint32_t b1 = *(const uint32_t*)&Kc[(nb * 8 + g) * 136 + kcol + 8];
                    mma_f16(sacc[nb], qf[ks], b0, b1);
                }
            }

            // Causal mask: only the diagonal 64-block (tiles i >= 2*qt).
            if (i >= 2 * qt) {
                const int row0 = m0 + r0q;
                const int row1 = row0 + 8;
                #pragma unroll
                for (int nb = 0; nb < 4; nb++) {
                    int c0 = n0 + nb * 8 + 2 * tg;
                    if (c0     > row0) sacc[nb][0] = -1e30f;
                    if (c0 + 1 > row0) sacc[nb][1] = -1e30f;
                    if (c0     > row1) sacc[nb][2] = -1e30f;
                    if (c0 + 1 > row1) sacc[nb][3] = -1e30f;
                }
            }

            // Online softmax; P stays in registers.
            float mx0 = -1e30f, mx1 = -1e30f;
            #pragma unroll
            for (int nb = 0; nb < 4; nb++) {
                mx0 = fmaxf(mx0, fmaxf(sacc[nb][0], sacc[nb][1]));
                mx1 = fmaxf(mx1, fmaxf(sacc[nb][2], sacc[nb][3]));
            }
            mx0 = fmaxf(mx0, __shfl_xor_sync(0xffffffffu, mx0, 1));
            mx0 = fmaxf(mx0, __shfl_xor_sync(0xffffffffu, mx0, 2));
            mx1 = fmaxf(mx1, __shfl_xor_sync(0xffffffffu, mx1, 1));
            mx1 = fmaxf(mx1, __shfl_xor_sync(0xffffffffu, mx1, 2));

            float mn0 = fmaxf(mrow0, mx0), mn1 = fmaxf(mrow1, mx1);
            float corr0 = __expf(mrow0 - mn0), corr1 = __expf(mrow1 - mn1);
            float rs0 = 0.f, rs1 = 0.f;
            uint32_t ph[4][2];
            #pragma unroll
            for (int nb = 0; nb < 4; nb++) {
                float p00 = __expf(sacc[nb][0] - mn0);
                float p01 = __expf(sacc[nb][1] - mn0);
                float p10 = __expf(sacc[nb][2] - mn1);
                float p11 = __expf(sacc[nb][3] - mn1);
                rs0 += p00 + p01;
                rs1 += p10 + p11;
                ph[nb][0] = h2u(p00, p01);
                ph[nb][1] = h2u(p10, p11);
            }
            rs0 += __shfl_xor_sync(0xffffffffu, rs0, 1);
            rs0 += __shfl_xor_sync(0xffffffffu, rs0, 2);
            rs1 += __shfl_xor_sync(0xffffffffu, rs1, 1);
            rs1 += __shfl_xor_sync(0xffffffffu, rs1, 2);
            lrow0 = lrow0 * corr0 + rs0;
            lrow1 = lrow1 * corr1 + rs1;
            mrow0 = mn0; mrow1 = mn1;
            #pragma unroll
            for (int nb = 0; nb < 16; nb++) {
                of[nb][0] *= corr0; of[nb][1] *= corr0;
                of[nb][2] *= corr1; of[nb][3] *= corr1;
            }

            // O += P . V  (P in registers as A-fragments).
            #pragma unroll
            for (int ks2 = 0; ks2 < 2; ks2++) {
                uint32_t pa[4] = { ph[2*ks2][0], ph[2*ks2][1],
                                   ph[2*ks2+1][0], ph[2*ks2+1][1] };
                #pragma unroll
                for (int nb = 0; nb < 16; nb++) {
                    uint32_t b0 = *(const uint32_t*)&Vc[(8*ks2 + tg    ) * 272 + (nb*8+g)*2];
                    uint32_t b1 = *(const uint32_t*)&Vc[(8*ks2 + tg + 4) * 272 + (nb*8+g)*2];
                    mma_f16(of[nb], pa, b0, b1);
                }
            }
        }

        const size_t obase = (size_t)t3 * BT * Hdim;
        const int grow = b * Tdim + m0 + r0q;
        #pragma unroll
        for (int nb = 0; nb < 16; nb++) {
            float2 lo = {of[nb][0], of[nb][1]};
            float2 hi = {of[nb][2], of[nb][3]};
            *(float2*)(g_Op + obase + (size_t)(grow    ) * Hdim + nb * 8 + 2 * tg) = lo;
            *(float2*)(g_Op + obase + (size_t)(grow + 8) * Hdim + nb * 8 + 2 * tg) = hi;
        }
        if (tg == 0) {
            g_m[t3 * BT + grow    ] = mrow0;
            g_l[t3 * BT + grow    ] = lrow0;
            g_m[t3 * BT + grow + 8] = mrow1;
            g_l[t3 * BT + grow + 8] = lrow1;
        }
    }
}

// ---------------------------------------------------------------------------
// Kernel 3: combine the three split-KV thirds.
// ---------------------------------------------------------------------------
__global__ __launch_bounds__(256) void combine_kernel(float* __restrict__ out)
{
    const int idx = blockIdx.x * 256 + threadIdx.x;
    const int row = idx >> 5;
    const int c4  = idx & 31;

    const float m0 = g_m[row], m1 = g_m[BT + row], m2 = g_m[2 * BT + row];
    const float l0 = g_l[row], l1 = g_l[BT + row], l2 = g_l[2 * BT + row];
    const float m  = fmaxf(m0, fmaxf(m1, m2));
    const float c0 = __expf(m0 - m);
    const float c1 = __expf(m1 - m);
    const float c2 = __expf(m2 - m);
    const float inv = 1.f / (c0 * l0 + c1 * l1 + c2 * l2);

    const float4 a = *(const float4*)(g_Op + (size_t)row * Hdim + c4 * 4);
    const float4 bb = *(const float4*)(g_Op + (size_t)BT * Hdim
                                       + (size_t)row * Hdim + c4 * 4);
    const float4 cc = *(const float4*)(g_Op + 2 * (size_t)BT * Hdim
                                       + (size_t)row * Hdim + c4 * 4);
    float4 r;
    r.x = (c0 * a.x + c1 * bb.x + c2 * cc.x) * inv;
    r.y = (c0 * a.y + c1 * bb.y + c2 * cc.y) * inv;
    r.z = (c0 * a.z + c1 * bb.z + c2 * cc.z) * inv;
    r.w = (c0 * a.w + c1 * bb.w + c2 * cc.w) * inv;
    *(float4*)(out + (size_t)row * Hdim + c4 * 4) = r;
}

// ---------------------------------------------------------------------------
extern "C" void kernel_launch(void* const* d_in, const int* in_sizes, int n_in,
                              void* d_out, int out_size)
{
    const float* x  = (const float*)d_in[0];
    const float* Wq = (const float*)d_in[1];
    const float* Wk = (const float*)d_in[2];
    const float* Wv = (const float*)d_in[3];
    float* out = (float*)d_out;

    xh_kernel<<<8192, 256>>>(x);
    wf_kernel<<<384, 256>>>(Wq, Wk, Wv);

    cudaFuncSetAttribute(qkv_kernel,
                         cudaFuncAttributeMaxDynamicSharedMemorySize, QKV_SMEM);
    qkv_kernel<<<dim3(BT / 128, 3), 128, QKV_SMEM>>>();

    cudaFuncSetAttribute(attn_kernel,
                         cudaFuncAttributeMaxDynamicSharedMemorySize, ATTN_SMEM);
    attn_kernel<<<dim3(48, Bdim), 128, ATTN_SMEM>>>();

    combine_kernel<<<(BT * Hdim / 4) / 256, 256>>>(out);
}

// round 13
// speedup vs baseline: 1.1274x; 1.1274x over previous
#include <cuda_runtime.h>
#include <cuda_fp16.h>
#include <cstdint>

#define Bdim 8
#define Tdim 2048
#define Cdim 1024
#define Hdim 128
#define BT (Bdim*Tdim)

// Scratch (device globals, allocation-free).
__device__ __half g_xh[BT * Cdim];            // x in fp16
__device__ uint2  g_Wf[3 * 16 * 4 * 16 * 32]; // W fragment-packed fp16 (Wq pre-scaled)
__device__ __half g_Qh[BT * Hdim];            // Q fp16 (pre-scaled via Wf)
__device__ __half g_Kh[BT * Hdim];            // K fp16
__device__ uint2  g_Vf[(BT / 64) * 2048];     // V fragment-packed per 64-row tile
__device__ float  g_Op[2 * BT * Hdim];        // unnormalized partial O per half
__device__ float  g_m[2 * BT];
__device__ float  g_l[2 * BT];

// ---------------------------------------------------------------------------
// Helpers
// ---------------------------------------------------------------------------
__device__ __forceinline__ uint32_t h2u(float a, float b) {
    __half2 h = __floats2half2_rn(a, b);
    return *(uint32_t*)&h;
}
__device__ __forceinline__ void mma_f16(float* d, const uint32_t* a,
                                        uint32_t b0, uint32_t b1) {
    asm volatile(
        "mma.sync.aligned.m16n8k16.row.col.f32.f16.f16.f32 "
        "{%0,%1,%2,%3}, {%4,%5,%6,%7}, {%8,%9}, {%0,%1,%2,%3};"
        : "+f"(d[0]), "+f"(d[1]), "+f"(d[2]), "+f"(d[3])
        : "r"(a[0]), "r"(a[1]), "r"(a[2]), "r"(a[3]), "r"(b0), "r"(b1));
}
__device__ __forceinline__ void ldsm_x4(uint32_t& r0, uint32_t& r1,
                                        uint32_t& r2, uint32_t& r3, uint32_t addr) {
    asm volatile("ldmatrix.sync.aligned.m8n8.x4.shared.b16 {%0,%1,%2,%3}, [%4];"
                 : "=r"(r0), "=r"(r1), "=r"(r2), "=r"(r3) : "r"(addr));
}
__device__ __forceinline__ uint32_t s2u(const void* p) {
    return (uint32_t)__cvta_generic_to_shared(p);
}
__device__ __forceinline__ void cpa16(uint32_t dst, const void* src) {
    asm volatile("cp.async.cg.shared.global [%0], [%1], 16;" :: "r"(dst), "l"(src));
}
__device__ __forceinline__ void cpa_commit() {
    asm volatile("cp.async.commit_group;");
}
__device__ __forceinline__ void cpa_wait0() {
    asm volatile("cp.async.wait_group 0;");
}

// ---------------------------------------------------------------------------
// Prologue A: x -> fp16.
// ---------------------------------------------------------------------------
__global__ __launch_bounds__(256) void xh_kernel(const float* __restrict__ x)
{
    const size_t i = (size_t)blockIdx.x * 256 + threadIdx.x;  // 0..2097151
    const float4 v0 = ((const float4*)x)[2 * i];
    const float4 v1 = ((const float4*)x)[2 * i + 1];
    uint4 p;
    p.x = h2u(v0.x, v0.y); p.y = h2u(v0.z, v0.w);
    p.z = h2u(v1.x, v1.y); p.w = h2u(v1.z, v1.w);
    ((uint4*)g_xh)[i] = p;
}

// ---------------------------------------------------------------------------
// Prologue B: W -> fragment-packed fp16 (Wq pre-scaled by 1/sqrt(128)).
// ---------------------------------------------------------------------------
__global__ __launch_bounds__(256) void wf_kernel(
    const float* __restrict__ Wq, const float* __restrict__ Wk,
    const float* __restrict__ Wv)
{
    const int t = blockIdx.x * 256 + threadIdx.x;   // 0..98303
    const int lane = t & 31;
    const int nb = (t >> 5) & 15;
    const int ks = (t >> 9) & 3;
    const int kc = (t >> 11) & 15;
    const int o  = t >> 15;
    const int g = lane >> 2, tg = lane & 3;
    const float* W = (o == 0) ? Wq : (o == 1) ? Wk : Wv;
    const float sc = (o == 0) ? 0.08838834764831845f : 1.f;
    const int K0 = kc * 64 + ks * 16;
    const int n  = nb * 8 + g;
    uint2 r;
    r.x = h2u(W[(size_t)(K0 + 2*tg    ) * Hdim + n] * sc,
              W[(size_t)(K0 + 2*tg + 1) * Hdim + n] * sc);
    r.y = h2u(W[(size_t)(K0 + 2*tg + 8) * Hdim + n] * sc,
              W[(size_t)(K0 + 2*tg + 9) * Hdim + n] * sc);
    g_Wf[t] = r;
}

// ---------------------------------------------------------------------------
// Kernel 1: QKV projection, fp16 m16n8k16, cp.async double-buffered, k-chunk 64.
// grid = (BT/128, 3), block = 128. Q/K row-major fp16; V fragment-packed.
// ---------------------------------------------------------------------------
#define QKV_SMEM 69632

__global__ __launch_bounds__(128, 3) void qkv_kernel()
{
    extern __shared__ char qsm[];
    __half* Ah[2] = { (__half*)qsm, (__half*)(qsm + 18432) };
    uint2*  Bf[2] = { (uint2*)(qsm + 36864), (uint2*)(qsm + 53248) };

    const int m0 = blockIdx.x * 128;
    const int o  = blockIdx.y;
    const int tid  = threadIdx.x;
    const int wid  = tid >> 5;
    const int lane = tid & 31;
    const int g    = lane >> 2;
    const int tg   = lane & 3;

    const __half* Ag = g_xh + (size_t)m0 * Cdim;
    const uint2*  Bg = g_Wf + (size_t)o * 16 * 2048;

    {
        uint32_t au = s2u(Ah[0]), bu = s2u(Bf[0]);
        #pragma unroll
        for (int t = 0; t < 8; t++) {
            int idx = t * 128 + tid;
            int row = idx >> 3, c = idx & 7;
            cpa16(au + row * 144 + c * 16, Ag + (size_t)row * Cdim + c * 8);
            cpa16(bu + idx * 16, (const char*)Bg + idx * 16);
        }
        cpa_commit();
    }

    float oc[2][16][4];
    #pragma unroll
    for (int mb = 0; mb < 2; mb++)
        #pragma unroll
        for (int nb = 0; nb < 16; nb++)
            #pragma unroll
            for (int c = 0; c < 4; c++) oc[mb][nb][c] = 0.f;

    #pragma unroll 1
    for (int kc = 0; kc < 16; kc++) {
        cpa_wait0();
        __syncthreads();
        const int cur = kc & 1;
        if (kc + 1 < 16) {
            uint32_t au = s2u(Ah[cur ^ 1]), bu = s2u(Bf[cur ^ 1]);
            const __half* Agn = Ag + (kc + 1) * 64;
            const uint2*  Bgn = Bg + (kc + 1) * 2048;
            #pragma unroll
            for (int t = 0; t < 8; t++) {
                int idx = t * 128 + tid;
                int row = idx >> 3, c = idx & 7;
                cpa16(au + row * 144 + c * 16, Agn + (size_t)row * Cdim + c * 8);
                cpa16(bu + idx * 16, (const char*)Bgn + idx * 16);
            }
            cpa_commit();
        }

        const __half* A = Ah[cur];
        const uint2*  B = Bf[cur];
        const int r0 = wid * 32 + g;
        #pragma unroll
        for (int ks = 0; ks < 4; ks++) {
            const int kcol = ks * 16 + 2 * tg;
            uint32_t a0[4], a1[4];
            a0[0] = *(const uint32_t*)&A[(r0     ) * 72 + kcol    ];
            a0[1] = *(const uint32_t*)&A[(r0 +  8) * 72 + kcol    ];
            a0[2] = *(const uint32_t*)&A[(r0     ) * 72 + kcol + 8];
            a0[3] = *(const uint32_t*)&A[(r0 +  8) * 72 + kcol + 8];
            a1[0] = *(const uint32_t*)&A[(r0 + 16) * 72 + kcol    ];
            a1[1] = *(const uint32_t*)&A[(r0 + 24) * 72 + kcol    ];
            a1[2] = *(const uint32_t*)&A[(r0 + 16) * 72 + kcol + 8];
            a1[3] = *(const uint32_t*)&A[(r0 + 24) * 72 + kcol + 8];
            #pragma unroll
            for (int nb = 0; nb < 16; nb++) {
                uint2 bb = B[(ks * 16 + nb) * 32 + lane];
                mma_f16(oc[0][nb], a0, bb.x, bb.y);
                mma_f16(oc[1][nb], a1, bb.x, bb.y);
            }
        }
    }

    if (o < 2) {
        __half* outp = (o == 0) ? g_Qh : g_Kh;
        #pragma unroll
        for (int mb = 0; mb < 2; mb++) {
            int r = m0 + wid * 32 + mb * 16 + g;
            #pragma unroll
            for (int nb = 0; nb < 16; nb++) {
                int col = nb * 8 + 2 * tg;
                *(uint32_t*)&outp[(size_t)(r    ) * Hdim + col] = h2u(oc[mb][nb][0], oc[mb][nb][1]);
                *(uint32_t*)&outp[(size_t)(r + 8) * Hdim + col] = h2u(oc[mb][nb][2], oc[mb][nb][3]);
            }
        }
    } else {
        // V: bounce through smem, emit fragment-packed layout for PV B operand.
        __syncthreads();
        __half* Vt = (__half*)qsm;   // [128][136]
        #pragma unroll
        for (int mb = 0; mb < 2; mb++) {
            int lr = wid * 32 + mb * 16 + g;
            #pragma unroll
            for (int nb = 0; nb < 16; nb++) {
                int col = nb * 8 + 2 * tg;
                *(uint32_t*)&Vt[(lr    ) * 136 + col] = h2u(oc[mb][nb][0], oc[mb][nb][1]);
                *(uint32_t*)&Vt[(lr + 8) * 136 + col] = h2u(oc[mb][nb][2], oc[mb][nb][3]);
            }
        }
        __syncthreads();
        const unsigned short* Vts = (const unsigned short*)Vt;
        #pragma unroll
        for (int q = 0; q < 32; q++) {
            int e = q * 128 + tid;           // 0..4095
            int t64 = e >> 11;               // 0..1
            int rem = e & 2047;
            int s   = rem >> 9;              // k16 block 0..3
            int nb  = (rem >> 5) & 15;
            int l   = rem & 31;
            int gg = l >> 2, tt = l & 3;
            int krow = t64 * 64 + s * 16 + 2 * tt;
            int n = nb * 8 + gg;
            uint2 rr;
            rr.x = (uint32_t)Vts[(krow    ) * 136 + n] |
                   ((uint32_t)Vts[(krow + 1) * 136 + n] << 16);
            rr.y = (uint32_t)Vts[(krow + 8) * 136 + n] |
                   ((uint32_t)Vts[(krow + 9) * 136 + n] << 16);
            g_Vf[(size_t)((m0 >> 6) + t64) * 2048 + rem] = rr;
        }
    }
}

// ---------------------------------------------------------------------------
// Kernel 2: causal flash attention, fp16 m16n8k16, split-KV + q-pairing,
// 64-wide kv tiles, ldmatrix K loads, fragment-packed V. Register-resident P.
// grid (32, 8): blockIdx.x = pair*2 + half. Half h takes 64-tiles of parity h.
// block = 128 (4 warps). Smem: K 2x[64][136]h (34816 B) + Vf 2x16384 B = 67584.
// ---------------------------------------------------------------------------
#define ATTN_SMEM 67584
#define K_BUF(i)  ((i) * 17408)
#define V_BUF(i)  (34816 + (i) * 16384)

__global__ __launch_bounds__(128) void attn_kernel()
{
    extern __shared__ char hsm[];
    const uint32_t sbase = s2u(hsm);

    const int p = (int)blockIdx.x >> 1;
    const int h = (int)blockIdx.x & 1;
    const int b = blockIdx.y;
    const int tid  = threadIdx.x;
    const int wid  = tid >> 5;
    const int lane = tid & 31;
    const int g    = lane >> 2;
    const int tg   = lane & 3;
    const int r0q  = wid * 16 + g;

    const __half* Qg = g_Qh + (size_t)b * Tdim * Hdim;
    const __half* Kg = g_Kh + (size_t)b * Tdim * Hdim;
    const uint2*  Vg = g_Vf + (size_t)b * 32 * 2048;   // 32 64-row tiles/batch

    // Per-lane LDSM row offsets for groups j (matrices: nb=2j+(m>>1), half=m&1).
    uint32_t krow_off[4];
    {
        const int m = lane >> 3, r = lane & 7;
        const int half = m & 1;
        #pragma unroll
        for (int j = 0; j < 4; j++) {
            int row = (2 * j + (m >> 1)) * 8 + r;
            krow_off[j] = (uint32_t)(row * 272 + half * 16);
        }
    }

    #pragma unroll 1
    for (int phase = 0; phase < 2; phase++) {
        const int qt = phase == 0 ? p : 31 - p;
        const int m0 = qt * 64;
        const int cnt = (qt >= h) ? ((qt - h) >> 1) + 1 : 0;  // 64-tiles, parity h

        __syncthreads();  // previous phase's smem fully consumed

        // Stage tile 0 (index h).
        if (cnt > 0) {
            const int i0 = h;
            uint32_t ku = sbase + K_BUF(0), vu = sbase + V_BUF(0);
            const __half* Ksrc = Kg + (size_t)(64 * i0) * Hdim;
            const char*   Vsrc = (const char*)(Vg + (size_t)i0 * 2048);
            #pragma unroll
            for (int t = 0; t < 8; t++) {
                int idx = t * 128 + tid;
                int krow = idx >> 4, kcc = idx & 15;
                cpa16(ku + krow * 272 + kcc * 16, Ksrc + (size_t)krow * Hdim + kcc * 8);
                cpa16(vu + idx * 16, Vsrc + idx * 16);
            }
            cpa_commit();
        }

        // Q fragments straight from global.
        uint32_t qf[8][4];
        {
            const __half* Qr0 = Qg + (size_t)(m0 + r0q) * Hdim;
            const __half* Qr1 = Qr0 + 8 * Hdim;
            #pragma unroll
            for (int ks = 0; ks < 8; ks++) {
                const int kcol = ks * 16 + 2 * tg;
                qf[ks][0] = __ldg((const uint32_t*)(Qr0 + kcol    ));
                qf[ks][1] = __ldg((const uint32_t*)(Qr1 + kcol    ));
                qf[ks][2] = __ldg((const uint32_t*)(Qr0 + kcol + 8));
                qf[ks][3] = __ldg((const uint32_t*)(Qr1 + kcol + 8));
            }
        }

        float of[16][4];
        #pragma unroll
        for (int nb = 0; nb < 16; nb++)
            #pragma unroll
            for (int c = 0; c < 4; c++) of[nb][c] = 0.f;
        float mrow0 = -1e30f, mrow1 = -1e30f, lrow0 = 0.f, lrow1 = 0.f;

        #pragma unroll 1
        for (int j = 0; j < cnt; j++) {
            const int cur = j & 1;
            const int i = 2 * j + h;       // 64-wide tile index
            cpa_wait0();
            __syncthreads();

            if (j + 1 < cnt) {
                const int in = 2 * (j + 1) + h;
                uint32_t ku = sbase + K_BUF(cur ^ 1), vu = sbase + V_BUF(cur ^ 1);
                const __half* Ksrc = Kg + (size_t)(64 * in) * Hdim;
                const char*   Vsrc = (const char*)(Vg + (size_t)in * 2048);
                #pragma unroll
                for (int t = 0; t < 8; t++) {
                    int idx = t * 128 + tid;
                    int krow = idx >> 4, kcc = idx & 15;
                    cpa16(ku + krow * 272 + kcc * 16, Ksrc + (size_t)krow * Hdim + kcc * 8);
                    cpa16(vu + idx * 16, Vsrc + idx * 16);
                }
                cpa_commit();
            }

            const uint32_t kbuf = sbase + K_BUF(cur);
            const char* VcB = hsm + V_BUF(cur);
            const int n0 = 64 * i;

            // S = Q . K^T  (16 q-rows x 64 kv per warp) via ldmatrix.x4.
            float sacc[8][4];
            #pragma unroll
            for (int nb = 0; nb < 8; nb++)
                #pragma unroll
                for (int c = 0; c < 4; c++) sacc[nb][c] = 0.f;

            #pragma unroll
            for (int ks = 0; ks < 8; ks++) {
                #pragma unroll
                for (int jj = 0; jj < 4; jj++) {
                    uint32_t b00, b01, b10, b11;
                    ldsm_x4(b00, b01, b10, b11, kbuf + krow_off[jj] + ks * 32);
                    mma_f16(sacc[2 * jj    ], qf[ks], b00, b01);
                    mma_f16(sacc[2 * jj + 1], qf[ks], b10, b11);
                }
            }

            // Causal mask (diagonal tile only; occurs iff qt parity == h).
            if (i == qt) {
                const int row0 = m0 + r0q;
                const int row1 = row0 + 8;
                #pragma unroll
                for (int nb = 0; nb < 8; nb++) {
                    int c0 = n0 + nb * 8 + 2 * tg;
                    if (c0     > row0) sacc[nb][0] = -1e30f;
                    if (c0 + 1 > row0) sacc[nb][1] = -1e30f;
                    if (c0     > row1) sacc[nb][2] = -1e30f;
                    if (c0 + 1 > row1) sacc[nb][3] = -1e30f;
                }
            }

            // Online softmax; P stays in registers.
            float mx0 = -1e30f, mx1 = -1e30f;
            #pragma unroll
            for (int nb = 0; nb < 8; nb++) {
                mx0 = fmaxf(mx0, fmaxf(sacc[nb][0], sacc[nb][1]));
                mx1 = fmaxf(mx1, fmaxf(sacc[nb][2], sacc[nb][3]));
            }
            mx0 = fmaxf(mx0, __shfl_xor_sync(0xffffffffu, mx0, 1));
            mx0 = fmaxf(mx0, __shfl_xor_sync(0xffffffffu, mx0, 2));
            mx1 = fmaxf(mx1, __shfl_xor_sync(0xffffffffu, mx1, 1));
            mx1 = fmaxf(mx1, __shfl_xor_sync(0xffffffffu, mx1, 2));

            float mn0 = fmaxf(mrow0, mx0), mn1 = fmaxf(mrow1, mx1);
            float corr0 = __expf(mrow0 - mn0), corr1 = __expf(mrow1 - mn1);
            float rs0 = 0.f, rs1 = 0.f;
            uint32_t ph[8][2];
            #pragma unroll
            for (int nb = 0; nb < 8; nb++) {
                float p00 = __expf(sacc[nb][0] - mn0);
                float p01 = __expf(sacc[nb][1] - mn0);
                float p10 = __expf(sacc[nb][2] - mn1);
                float p11 = __expf(sacc[nb][3] - mn1);
                rs0 += p00 + p01;
                rs1 += p10 + p11;
                ph[nb][0] = h2u(p00, p01);
                ph[nb][1] = h2u(p10, p11);
            }
            rs0 += __shfl_xor_sync(0xffffffffu, rs0, 1);
            rs0 += __shfl_xor_sync(0xffffffffu, rs0, 2);
            rs1 += __shfl_xor_sync(0xffffffffu, rs1, 1);
            rs1 += __shfl_xor_sync(0xffffffffu, rs1, 2);
            lrow0 = lrow0 * corr0 + rs0;
            lrow1 = lrow1 * corr1 + rs1;
            mrow0 = mn0; mrow1 = mn1;
            #pragma unroll
            for (int nb = 0; nb < 16; nb++) {
                of[nb][0] *= corr0; of[nb][1] *= corr0;
                of[nb][2] *= corr1; of[nb][3] *= corr1;
            }

            // O += P . V  (P in registers; V fragment-packed, k = 64).
            #pragma unroll
            for (int ks2 = 0; ks2 < 4; ks2++) {
                uint32_t pa[4] = { ph[2*ks2][0], ph[2*ks2][1],
                                   ph[2*ks2+1][0], ph[2*ks2+1][1] };
                #pragma unroll
                for (int nb = 0; nb < 16; nb++) {
                    uint2 bb = *(const uint2*)(VcB + (((ks2 * 16 + nb) * 32 + lane) << 3));
                    mma_f16(of[nb], pa, bb.x, bb.y);
                }
            }
        }

        const size_t obase = (size_t)h * BT * Hdim;
        const int grow = b * Tdim + m0 + r0q;
        #pragma unroll
        for (int nb = 0; nb < 16; nb++) {
            float2 lo = {of[nb][0], of[nb][1]};
            float2 hi = {of[nb][2], of[nb][3]};
            *(float2*)(g_Op + obase + (size_t)(grow    ) * Hdim + nb * 8 + 2 * tg) = lo;
            *(float2*)(g_Op + obase + (size_t)(grow + 8) * Hdim + nb * 8 + 2 * tg) = hi;
        }
        if (tg == 0) {
            g_m[h * BT + grow    ] = mrow0;
            g_l[h * BT + grow    ] = lrow0;
            g_m[h * BT + grow + 8] = mrow1;
            g_l[h * BT + grow + 8] = lrow1;
        }
    }
}

// ---------------------------------------------------------------------------
// Kernel 3: combine the two split-KV halves.
// ---------------------------------------------------------------------------
__global__ __launch_bounds__(256) void combine_kernel(float* __restrict__ out)
{
    const int idx = blockIdx.x * 256 + threadIdx.x;
    const int row = idx >> 5;
    const int c4  = idx & 31;

    const float m0 = g_m[row], m1 = g_m[BT + row];
    const float l0 = g_l[row], l1 = g_l[BT + row];
    const float m  = fmaxf(m0, m1);
    const float c0 = __expf(m0 - m);
    const float c1 = __expf(m1 - m);
    const float inv = 1.f / (c0 * l0 + c1 * l1);

    const float4 a = *(const float4*)(g_Op + (size_t)row * Hdim + c4 * 4);
    const float4 bb = *(const float4*)(g_Op + (size_t)BT * Hdim
                                       + (size_t)row * Hdim + c4 * 4);
    float4 r;
    r.x = (c0 * a.x + c1 * bb.x) * inv;
    r.y = (c0 * a.y + c1 * bb.y) * inv;
    r.z = (c0 * a.z + c1 * bb.z) * inv;
    r.w = (c0 * a.w + c1 * bb.w) * inv;
    *(float4*)(out + (size_t)row * Hdim + c4 * 4) = r;
}

// ---------------------------------------------------------------------------
extern "C" void kernel_launch(void* const* d_in, const int* in_sizes, int n_in,
                              void* d_out, int out_size)
{
    const float* x  = (const float*)d_in[0];
    const float* Wq = (const float*)d_in[1];
    const float* Wk = (const float*)d_in[2];
    const float* Wv = (const float*)d_in[3];
    float* out = (float*)d_out;

    xh_kernel<<<8192, 256>>>(x);
    wf_kernel<<<384, 256>>>(Wq, Wk, Wv);

    cudaFuncSetAttribute(qkv_kernel,
                         cudaFuncAttributeMaxDynamicSharedMemorySize, QKV_SMEM);
    qkv_kernel<<<dim3(BT / 128, 3), 128, QKV_SMEM>>>();

    cudaFuncSetAttribute(attn_kernel,
                         cudaFuncAttributeMaxDynamicSharedMemorySize, ATTN_SMEM);
    attn_kernel<<<dim3(32, Bdim), 128, ATTN_SMEM>>>();

    combine_kernel<<<(BT * Hdim / 4) / 256, 256>>>(out);
}

// round 14
// speedup vs baseline: 1.1328x; 1.0048x over previous
#include <cuda_runtime.h>
#include <cuda_fp16.h>
#include <cstdint>

#define Bdim 8
#define Tdim 2048
#define Cdim 1024
#define Hdim 128
#define BT (Bdim*Tdim)

// Scratch (device globals, allocation-free).
__device__ __half g_xh[BT * Cdim];            // x in fp16
__device__ uint2  g_Wf[3 * 16 * 4 * 16 * 32]; // W fragment-packed fp16 (Wq pre-scaled by log2e/sqrt(H))
__device__ __half g_Qh[BT * Hdim];            // Q fp16 (pre-scaled, log2 domain)
__device__ __half g_Kh[BT * Hdim];            // K fp16
__device__ uint2  g_Vf[(BT / 64) * 2048];     // V fragment-packed per 64-row tile
__device__ float  g_Op[2 * BT * Hdim];        // unnormalized partial O per half
__device__ float  g_m[2 * BT];                // row max (log2 domain)
__device__ float  g_l[2 * BT];

// ---------------------------------------------------------------------------
// Helpers
// ---------------------------------------------------------------------------
__device__ __forceinline__ uint32_t h2u(float a, float b) {
    __half2 h = __floats2half2_rn(a, b);
    return *(uint32_t*)&h;
}
__device__ __forceinline__ void mma_f16(float* d, const uint32_t* a,
                                        uint32_t b0, uint32_t b1) {
    asm volatile(
        "mma.sync.aligned.m16n8k16.row.col.f32.f16.f16.f32 "
        "{%0,%1,%2,%3}, {%4,%5,%6,%7}, {%8,%9}, {%0,%1,%2,%3};"
        : "+f"(d[0]), "+f"(d[1]), "+f"(d[2]), "+f"(d[3])
        : "r"(a[0]), "r"(a[1]), "r"(a[2]), "r"(a[3]), "r"(b0), "r"(b1));
}
__device__ __forceinline__ void ldsm_x4(uint32_t& r0, uint32_t& r1,
                                        uint32_t& r2, uint32_t& r3, uint32_t addr) {
    asm volatile("ldmatrix.sync.aligned.m8n8.x4.shared.b16 {%0,%1,%2,%3}, [%4];"
                 : "=r"(r0), "=r"(r1), "=r"(r2), "=r"(r3) : "r"(addr));
}
__device__ __forceinline__ uint32_t s2u(const void* p) {
    return (uint32_t)__cvta_generic_to_shared(p);
}
__device__ __forceinline__ void cpa16(uint32_t dst, const void* src) {
    asm volatile("cp.async.cg.shared.global [%0], [%1], 16;" :: "r"(dst), "l"(src));
}
__device__ __forceinline__ void cpa_commit() {
    asm volatile("cp.async.commit_group;");
}
__device__ __forceinline__ void cpa_wait0() {
    asm volatile("cp.async.wait_group 0;");
}

// ---------------------------------------------------------------------------
// Prologue A: x -> fp16.
// ---------------------------------------------------------------------------
__global__ __launch_bounds__(256) void xh_kernel(const float* __restrict__ x)
{
    const size_t i = (size_t)blockIdx.x * 256 + threadIdx.x;  // 0..2097151
    const float4 v0 = ((const float4*)x)[2 * i];
    const float4 v1 = ((const float4*)x)[2 * i + 1];
    uint4 p;
    p.x = h2u(v0.x, v0.y); p.y = h2u(v0.z, v0.w);
    p.z = h2u(v1.x, v1.y); p.w = h2u(v1.z, v1.w);
    ((uint4*)g_xh)[i] = p;
}

// ---------------------------------------------------------------------------
// Prologue B: W -> fragment-packed fp16.
// Wq pre-scaled by log2(e)/sqrt(128) so attention works in the exp2 domain.
// ---------------------------------------------------------------------------
__global__ __launch_bounds__(256) void wf_kernel(
    const float* __restrict__ Wq, const float* __restrict__ Wk,
    const float* __restrict__ Wv)
{
    const int t = blockIdx.x * 256 + threadIdx.x;   // 0..98303
    const int lane = t & 31;
    const int nb = (t >> 5) & 15;
    const int ks = (t >> 9) & 3;
    const int kc = (t >> 11) & 15;
    const int o  = t >> 15;
    const int g = lane >> 2, tg = lane & 3;
    const float* W = (o == 0) ? Wq : (o == 1) ? Wk : Wv;
    const float sc = (o == 0) ? 0.12751744f : 1.f;   // log2e / sqrt(128)
    const int K0 = kc * 64 + ks * 16;
    const int n  = nb * 8 + g;
    uint2 r;
    r.x = h2u(W[(size_t)(K0 + 2*tg    ) * Hdim + n] * sc,
              W[(size_t)(K0 + 2*tg + 1) * Hdim + n] * sc);
    r.y = h2u(W[(size_t)(K0 + 2*tg + 8) * Hdim + n] * sc,
              W[(size_t)(K0 + 2*tg + 9) * Hdim + n] * sc);
    g_Wf[t] = r;
}

// ---------------------------------------------------------------------------
// Kernel 1: QKV projection, fp16 m16n8k16, cp.async double-buffered, k-chunk 64.
// A fragments via ldmatrix.x4 (row stride 144 B -> conflict-free).
// grid = (BT/128, 3), block = 128. Q/K row-major fp16; V fragment-packed.
// ---------------------------------------------------------------------------
#define QKV_SMEM 69632

__global__ __launch_bounds__(128, 3) void qkv_kernel()
{
    extern __shared__ char qsm[];
    __half* Ah[2] = { (__half*)qsm, (__half*)(qsm + 18432) };
    uint2*  Bf[2] = { (uint2*)(qsm + 36864), (uint2*)(qsm + 53248) };

    const int m0 = blockIdx.x * 128;
    const int o  = blockIdx.y;
    const int tid  = threadIdx.x;
    const int wid  = tid >> 5;
    const int lane = tid & 31;
    const int g    = lane >> 2;
    const int tg   = lane & 3;

    const __half* Ag = g_xh + (size_t)m0 * Cdim;
    const uint2*  Bg = g_Wf + (size_t)o * 16 * 2048;

    // ldmatrix per-lane base offset within the A tile (bytes):
    // row = wid*32 + (lane&15) [+16 for mb=1], k-half = (lane>>4)*16 bytes.
    const uint32_t a_off = (uint32_t)((wid * 32 + (lane & 15)) * 144 + (lane >> 4) * 16);

    {
        uint32_t au = s2u(Ah[0]), bu = s2u(Bf[0]);
        #pragma unroll
        for (int t = 0; t < 8; t++) {
            int idx = t * 128 + tid;
            int row = idx >> 3, c = idx & 7;
            cpa16(au + row * 144 + c * 16, Ag + (size_t)row * Cdim + c * 8);
            cpa16(bu + idx * 16, (const char*)Bg + idx * 16);
        }
        cpa_commit();
    }

    float oc[2][16][4];
    #pragma unroll
    for (int mb = 0; mb < 2; mb++)
        #pragma unroll
        for (int nb = 0; nb < 16; nb++)
            #pragma unroll
            for (int c = 0; c < 4; c++) oc[mb][nb][c] = 0.f;

    #pragma unroll 1
    for (int kc = 0; kc < 16; kc++) {
        cpa_wait0();
        __syncthreads();
        const int cur = kc & 1;
        if (kc + 1 < 16) {
            uint32_t au = s2u(Ah[cur ^ 1]), bu = s2u(Bf[cur ^ 1]);
            const __half* Agn = Ag + (kc + 1) * 64;
            const uint2*  Bgn = Bg + (kc + 1) * 2048;
            #pragma unroll
            for (int t = 0; t < 8; t++) {
                int idx = t * 128 + tid;
                int row = idx >> 3, c = idx & 7;
                cpa16(au + row * 144 + c * 16, Agn + (size_t)row * Cdim + c * 8);
                cpa16(bu + idx * 16, (const char*)Bgn + idx * 16);
            }
            cpa_commit();
        }

        const uint32_t abase = s2u(Ah[cur]) + a_off;
        const uint2* B = Bf[cur];
        #pragma unroll
        for (int ks = 0; ks < 4; ks++) {
            uint32_t a0[4], a1[4];
            ldsm_x4(a0[0], a0[1], a0[2], a0[3], abase + ks * 32);
            ldsm_x4(a1[0], a1[1], a1[2], a1[3], abase + 16 * 144 + ks * 32);
            #pragma unroll
            for (int nb = 0; nb < 16; nb++) {
                uint2 bb = B[(ks * 16 + nb) * 32 + lane];
                mma_f16(oc[0][nb], a0, bb.x, bb.y);
                mma_f16(oc[1][nb], a1, bb.x, bb.y);
            }
        }
    }

    if (o < 2) {
        __half* outp = (o == 0) ? g_Qh : g_Kh;
        #pragma unroll
        for (int mb = 0; mb < 2; mb++) {
            int r = m0 + wid * 32 + mb * 16 + g;
            #pragma unroll
            for (int nb = 0; nb < 16; nb++) {
                int col = nb * 8 + 2 * tg;
                *(uint32_t*)&outp[(size_t)(r    ) * Hdim + col] = h2u(oc[mb][nb][0], oc[mb][nb][1]);
                *(uint32_t*)&outp[(size_t)(r + 8) * Hdim + col] = h2u(oc[mb][nb][2], oc[mb][nb][3]);
            }
        }
    } else {
        // V: bounce through smem, emit fragment-packed layout for PV B operand.
        __syncthreads();
        __half* Vt = (__half*)qsm;   // [128][136]
        #pragma unroll
        for (int mb = 0; mb < 2; mb++) {
            int lr = wid * 32 + mb * 16 + g;
            #pragma unroll
            for (int nb = 0; nb < 16; nb++) {
                int col = nb * 8 + 2 * tg;
                *(uint32_t*)&Vt[(lr    ) * 136 + col] = h2u(oc[mb][nb][0], oc[mb][nb][1]);
                *(uint32_t*)&Vt[(lr + 8) * 136 + col] = h2u(oc[mb][nb][2], oc[mb][nb][3]);
            }
        }
        __syncthreads();
        const unsigned short* Vts = (const unsigned short*)Vt;
        #pragma unroll
        for (int q = 0; q < 32; q++) {
            int e = q * 128 + tid;           // 0..4095
            int t64 = e >> 11;               // 0..1
            int rem = e & 2047;
            int s   = rem >> 9;              // k16 block 0..3
            int nb  = (rem >> 5) & 15;
            int l   = rem & 31;
            int gg = l >> 2, tt = l & 3;
            int krow = t64 * 64 + s * 16 + 2 * tt;
            int n = nb * 8 + gg;
            uint2 rr;
            rr.x = (uint32_t)Vts[(krow    ) * 136 + n] |
                   ((uint32_t)Vts[(krow + 1) * 136 + n] << 16);
            rr.y = (uint32_t)Vts[(krow + 8) * 136 + n] |
                   ((uint32_t)Vts[(krow + 9) * 136 + n] << 16);
            g_Vf[(size_t)((m0 >> 6) + t64) * 2048 + rem] = rr;
        }
    }
}

// ---------------------------------------------------------------------------
// Kernel 2: causal flash attention, fp16 m16n8k16, split-KV + q-pairing,
// 64-wide kv tiles, ldmatrix K loads, fragment-packed V, exp2-domain softmax.
// grid (32, 8): blockIdx.x = pair*2 + half. Half h takes 64-tiles of parity h.
// block = 128 (4 warps). Smem: K 2x[64][136]h (34816 B) + Vf 2x16384 B = 67584.
// ---------------------------------------------------------------------------
#define ATTN_SMEM 67584
#define K_BUF(i)  ((i) * 17408)
#define V_BUF(i)  (34816 + (i) * 16384)

__global__ __launch_bounds__(128) void attn_kernel()
{
    extern __shared__ char hsm[];
    const uint32_t sbase = s2u(hsm);

    const int p = (int)blockIdx.x >> 1;
    const int h = (int)blockIdx.x & 1;
    const int b = blockIdx.y;
    const int tid  = threadIdx.x;
    const int wid  = tid >> 5;
    const int lane = tid & 31;
    const int g    = lane >> 2;
    const int tg   = lane & 3;
    const int r0q  = wid * 16 + g;

    const __half* Qg = g_Qh + (size_t)b * Tdim * Hdim;
    const __half* Kg = g_Kh + (size_t)b * Tdim * Hdim;
    const uint2*  Vg = g_Vf + (size_t)b * 32 * 2048;   // 32 64-row tiles/batch

    // Per-lane LDSM row offsets for groups j (matrices: nb=2j+(m>>1), half=m&1).
    uint32_t krow_off[4];
    {
        const int m = lane >> 3, r = lane & 7;
        const int half = m & 1;
        #pragma unroll
        for (int j = 0; j < 4; j++) {
            int row = (2 * j + (m >> 1)) * 8 + r;
            krow_off[j] = (uint32_t)(row * 272 + half * 16);
        }
    }

    #pragma unroll 1
    for (int phase = 0; phase < 2; phase++) {
        const int qt = phase == 0 ? p : 31 - p;
        const int m0 = qt * 64;
        const int cnt = (qt >= h) ? ((qt - h) >> 1) + 1 : 0;  // 64-tiles, parity h

        __syncthreads();  // previous phase's smem fully consumed

        // Stage tile 0 (index h).
        if (cnt > 0) {
            const int i0 = h;
            uint32_t ku = sbase + K_BUF(0), vu = sbase + V_BUF(0);
            const __half* Ksrc = Kg + (size_t)(64 * i0) * Hdim;
            const char*   Vsrc = (const char*)(Vg + (size_t)i0 * 2048);
            #pragma unroll
            for (int t = 0; t < 8; t++) {
                int idx = t * 128 + tid;
                int krow = idx >> 4, kcc = idx & 15;
                cpa16(ku + krow * 272 + kcc * 16, Ksrc + (size_t)krow * Hdim + kcc * 8);
                cpa16(vu + idx * 16, Vsrc + idx * 16);
            }
            cpa_commit();
        }

        // Q fragments straight from global.
        uint32_t qf[8][4];
        {
            const __half* Qr0 = Qg + (size_t)(m0 + r0q) * Hdim;
            const __half* Qr1 = Qr0 + 8 * Hdim;
            #pragma unroll
            for (int ks = 0; ks < 8; ks++) {
                const int kcol = ks * 16 + 2 * tg;
                qf[ks][0] = __ldg((const uint32_t*)(Qr0 + kcol    ));
                qf[ks][1] = __ldg((const uint32_t*)(Qr1 + kcol    ));
                qf[ks][2] = __ldg((const uint32_t*)(Qr0 + kcol + 8));
                qf[ks][3] = __ldg((const uint32_t*)(Qr1 + kcol + 8));
            }
        }

        float of[16][4];
        #pragma unroll
        for (int nb = 0; nb < 16; nb++)
            #pragma unroll
            for (int c = 0; c < 4; c++) of[nb][c] = 0.f;
        float mrow0 = -1e30f, mrow1 = -1e30f, lrow0 = 0.f, lrow1 = 0.f;

        #pragma unroll 1
        for (int j = 0; j < cnt; j++) {
            const int cur = j & 1;
            const int i = 2 * j + h;       // 64-wide tile index
            cpa_wait0();
            __syncthreads();

            if (j + 1 < cnt) {
                const int in = 2 * (j + 1) + h;
                uint32_t ku = sbase + K_BUF(cur ^ 1), vu = sbase + V_BUF(cur ^ 1);
                const __half* Ksrc = Kg + (size_t)(64 * in) * Hdim;
                const char*   Vsrc = (const char*)(Vg + (size_t)in * 2048);
                #pragma unroll
                for (int t = 0; t < 8; t++) {
                    int idx = t * 128 + tid;
                    int krow = idx >> 4, kcc = idx & 15;
                    cpa16(ku + krow * 272 + kcc * 16, Ksrc + (size_t)krow * Hdim + kcc * 8);
                    cpa16(vu + idx * 16, Vsrc + idx * 16);
                }
                cpa_commit();
            }

            const uint32_t kbuf = sbase + K_BUF(cur);
            const char* VcB = hsm + V_BUF(cur);
            const int n0 = 64 * i;

            // S = Q . K^T  (16 q-rows x 64 kv per warp) via ldmatrix.x4.
            float sacc[8][4];
            #pragma unroll
            for (int nb = 0; nb < 8; nb++)
                #pragma unroll
                for (int c = 0; c < 4; c++) sacc[nb][c] = 0.f;

            #pragma unroll
            for (int ks = 0; ks < 8; ks++) {
                #pragma unroll
                for (int jj = 0; jj < 4; jj++) {
                    uint32_t b00, b01, b10, b11;
                    ldsm_x4(b00, b01, b10, b11, kbuf + krow_off[jj] + ks * 32);
                    mma_f16(sacc[2 * jj    ], qf[ks], b00, b01);
                    mma_f16(sacc[2 * jj + 1], qf[ks], b10, b11);
                }
            }

            // Causal mask (diagonal tile only; occurs iff qt parity == h).
            if (i == qt) {
                const int row0 = m0 + r0q;
                const int row1 = row0 + 8;
                #pragma unroll
                for (int nb = 0; nb < 8; nb++) {
                    int c0 = n0 + nb * 8 + 2 * tg;
                    if (c0     > row0) sacc[nb][0] = -1e30f;
                    if (c0 + 1 > row0) sacc[nb][1] = -1e30f;
                    if (c0     > row1) sacc[nb][2] = -1e30f;
                    if (c0 + 1 > row1) sacc[nb][3] = -1e30f;
                }
            }

            // Online softmax in exp2 domain; P stays in registers.
            float mx0 = -1e30f, mx1 = -1e30f;
            #pragma unroll
            for (int nb = 0; nb < 8; nb++) {
                mx0 = fmaxf(mx0, fmaxf(sacc[nb][0], sacc[nb][1]));
                mx1 = fmaxf(mx1, fmaxf(sacc[nb][2], sacc[nb][3]));
            }
            mx0 = fmaxf(mx0, __shfl_xor_sync(0xffffffffu, mx0, 1));
            mx0 = fmaxf(mx0, __shfl_xor_sync(0xffffffffu, mx0, 2));
            mx1 = fmaxf(mx1, __shfl_xor_sync(0xffffffffu, mx1, 1));
            mx1 = fmaxf(mx1, __shfl_xor_sync(0xffffffffu, mx1, 2));

            float mn0 = fmaxf(mrow0, mx0), mn1 = fmaxf(mrow1, mx1);
            float corr0 = exp2f(mrow0 - mn0), corr1 = exp2f(mrow1 - mn1);
            float rs0 = 0.f, rs1 = 0.f;
            uint32_t ph[8][2];
            #pragma unroll
            for (int nb = 0; nb < 8; nb++) {
                float p00 = exp2f(sacc[nb][0] - mn0);
                float p01 = exp2f(sacc[nb][1] - mn0);
                float p10 = exp2f(sacc[nb][2] - mn1);
                float p11 = exp2f(sacc[nb][3] - mn1);
                rs0 += p00 + p01;
                rs1 += p10 + p11;
                ph[nb][0] = h2u(p00, p01);
                ph[nb][1] = h2u(p10, p11);
            }
            rs0 += __shfl_xor_sync(0xffffffffu, rs0, 1);
            rs0 += __shfl_xor_sync(0xffffffffu, rs0, 2);
            rs1 += __shfl_xor_sync(0xffffffffu, rs1, 1);
            rs1 += __shfl_xor_sync(0xffffffffu, rs1, 2);
            lrow0 = lrow0 * corr0 + rs0;
            lrow1 = lrow1 * corr1 + rs1;
            mrow0 = mn0; mrow1 = mn1;
            #pragma unroll
            for (int nb = 0; nb < 16; nb++) {
                of[nb][0] *= corr0; of[nb][1] *= corr0;
                of[nb][2] *= corr1; of[nb][3] *= corr1;
            }

            // O += P . V  (P in registers; V fragment-packed, k = 64).
            #pragma unroll
            for (int ks2 = 0; ks2 < 4; ks2++) {
                uint32_t pa[4] = { ph[2*ks2][0], ph[2*ks2][1],
                                   ph[2*ks2+1][0], ph[2*ks2+1][1] };
                #pragma unroll
                for (int nb = 0; nb < 16; nb++) {
                    uint2 bb = *(const uint2*)(VcB + (((ks2 * 16 + nb) * 32 + lane) << 3));
                    mma_f16(of[nb], pa, bb.x, bb.y);
                }
            }
        }

        const size_t obase = (size_t)h * BT * Hdim;
        const int grow = b * Tdim + m0 + r0q;
        #pragma unroll
        for (int nb = 0; nb < 16; nb++) {
            float2 lo = {of[nb][0], of[nb][1]};
            float2 hi = {of[nb][2], of[nb][3]};
            *(float2*)(g_Op + obase + (size_t)(grow    ) * Hdim + nb * 8 + 2 * tg) = lo;
            *(float2*)(g_Op + obase + (size_t)(grow + 8) * Hdim + nb * 8 + 2 * tg) = hi;
        }
        if (tg == 0) {
            g_m[h * BT + grow    ] = mrow0;
            g_l[h * BT + grow    ] = lrow0;
            g_m[h * BT + grow + 8] = mrow1;
            g_l[h * BT + grow + 8] = lrow1;
        }
    }
}

// ---------------------------------------------------------------------------
// Kernel 3: combine the two split-KV halves (exp2 domain).
// ---------------------------------------------------------------------------
__global__ __launch_bounds__(256) void combine_kernel(float* __restrict__ out)
{
    const int idx = blockIdx.x * 256 + threadIdx.x;
    const int row = idx >> 5;
    const int c4  = idx & 31;

    const float m0 = g_m[row], m1 = g_m[BT + row];
    const float l0 = g_l[row], l1 = g_l[BT + row];
    const float m  = fmaxf(m0, m1);
    const float c0 = exp2f(m0 - m);
    const float c1 = exp2f(m1 - m);
    const float inv = 1.f / (c0 * l0 + c1 * l1);

    const float4 a = *(const float4*)(g_Op + (size_t)row * Hdim + c4 * 4);
    const float4 bb = *(const float4*)(g_Op + (size_t)BT * Hdim
                                       + (size_t)row * Hdim + c4 * 4);
    float4 r;
    r.x = (c0 * a.x + c1 * bb.x) * inv;
    r.y = (c0 * a.y + c1 * bb.y) * inv;
    r.z = (c0 * a.z + c1 * bb.z) * inv;
    r.w = (c0 * a.w + c1 * bb.w) * inv;
    *(float4*)(out + (size_t)row * Hdim + c4 * 4) = r;
}

// ---------------------------------------------------------------------------
extern "C" void kernel_launch(void* const* d_in, const int* in_sizes, int n_in,
                              void* d_out, int out_size)
{
    const float* x  = (const float*)d_in[0];
    const float* Wq = (const float*)d_in[1];
    const float* Wk = (const float*)d_in[2];
    const float* Wv = (const float*)d_in[3];
    float* out = (float*)d_out;

    xh_kernel<<<8192, 256>>>(x);
    wf_kernel<<<384, 256>>>(Wq, Wk, Wv);

    cudaFuncSetAttribute(qkv_kernel,
                         cudaFuncAttributeMaxDynamicSharedMemorySize, QKV_SMEM);
    qkv_kernel<<<dim3(BT / 128, 3), 128, QKV_SMEM>>>();

    cudaFuncSetAttribute(attn_kernel,
                         cudaFuncAttributeMaxDynamicSharedMemorySize, ATTN_SMEM);
    attn_kernel<<<dim3(32, Bdim), 128, ATTN_SMEM>>>();

    combine_kernel<<<(BT * Hdim / 4) / 256, 256>>>(out);
}

// round 15
// speedup vs baseline: 1.2242x; 1.0807x over previous
#include <cuda_runtime.h>
#include <cuda_fp16.h>
#include <cstdint>

#define Bdim 8
#define Tdim 2048
#define Cdim 1024
#define Hdim 128
#define BT (Bdim*Tdim)

// Scratch (device globals, allocation-free).
__device__ uint2  g_Wf[3 * 16 * 4 * 16 * 32]; // W fragment-packed fp16 (Wq pre-scaled by log2e/sqrt(H))
__device__ __half g_Qh[BT * Hdim];            // Q fp16 (pre-scaled, log2 domain)
__device__ __half g_Kh[BT * Hdim];            // K fp16
__device__ uint2  g_Vf[(BT / 64) * 2048];     // V fragment-packed per 64-row tile
__device__ float  g_Op[2 * BT * Hdim];        // unnormalized partial O per half
__device__ float  g_m[2 * BT];                // row max (log2 domain)
__device__ float  g_l[2 * BT];

// ---------------------------------------------------------------------------
// Helpers
// ---------------------------------------------------------------------------
__device__ __forceinline__ uint32_t h2u(float a, float b) {
    __half2 h = __floats2half2_rn(a, b);
    return *(uint32_t*)&h;
}
__device__ __forceinline__ void mma_f16(float* d, const uint32_t* a,
                                        uint32_t b0, uint32_t b1) {
    asm volatile(
        "mma.sync.aligned.m16n8k16.row.col.f32.f16.f16.f32 "
        "{%0,%1,%2,%3}, {%4,%5,%6,%7}, {%8,%9}, {%0,%1,%2,%3};"
        : "+f"(d[0]), "+f"(d[1]), "+f"(d[2]), "+f"(d[3])
        : "r"(a[0]), "r"(a[1]), "r"(a[2]), "r"(a[3]), "r"(b0), "r"(b1));
}
__device__ __forceinline__ void ldsm_x4(uint32_t& r0, uint32_t& r1,
                                        uint32_t& r2, uint32_t& r3, uint32_t addr) {
    asm volatile("ldmatrix.sync.aligned.m8n8.x4.shared.b16 {%0,%1,%2,%3}, [%4];"
                 : "=r"(r0), "=r"(r1), "=r"(r2), "=r"(r3) : "r"(addr));
}
__device__ __forceinline__ uint32_t s2u(const void* p) {
    return (uint32_t)__cvta_generic_to_shared(p);
}
__device__ __forceinline__ void cpa16(uint32_t dst, const void* src) {
    asm volatile("cp.async.cg.shared.global [%0], [%1], 16;" :: "r"(dst), "l"(src));
}
__device__ __forceinline__ void cpa_commit() {
    asm volatile("cp.async.commit_group;");
}
__device__ __forceinline__ void cpa_wait0() {
    asm volatile("cp.async.wait_group 0;");
}

// ---------------------------------------------------------------------------
// Prologue: W -> fragment-packed fp16.
// Wq pre-scaled by log2(e)/sqrt(128) so attention works in the exp2 domain.
// ---------------------------------------------------------------------------
__global__ __launch_bounds__(256) void wf_kernel(
    const float* __restrict__ Wq, const float* __restrict__ Wk,
    const float* __restrict__ Wv)
{
    const int t = blockIdx.x * 256 + threadIdx.x;   // 0..98303
    const int lane = t & 31;
    const int nb = (t >> 5) & 15;
    const int ks = (t >> 9) & 3;
    const int kc = (t >> 11) & 15;
    const int o  = t >> 15;
    const int g = lane >> 2, tg = lane & 3;
    const float* W = (o == 0) ? Wq : (o == 1) ? Wk : Wv;
    const float sc = (o == 0) ? 0.12751744f : 1.f;   // log2e / sqrt(128)
    const int K0 = kc * 64 + ks * 16;
    const int n  = nb * 8 + g;
    uint2 r;
    r.x = h2u(W[(size_t)(K0 + 2*tg    ) * Hdim + n] * sc,
              W[(size_t)(K0 + 2*tg + 1) * Hdim + n] * sc);
    r.y = h2u(W[(size_t)(K0 + 2*tg + 8) * Hdim + n] * sc,
              W[(size_t)(K0 + 2*tg + 9) * Hdim + n] * sc);
    g_Wf[t] = r;
}

// ---------------------------------------------------------------------------
// Kernel 1: FUSED QKV projection. x read ONCE per m-tile as fp32 (cp.async),
// converted to fp16 at fragment build. All three W fragment sets staged.
// grid = BT/128, block = 384 (12 warps: warp w -> output o=w>>2, rows (w&3)*32).
// Smem: A fp32 [2][128][68] (34816 B each) + B frag [2][3][16 KB] (49152 each)
//       = 167936 B -> 1 CTA/SM. Q/K row-major fp16; V fragment-packed.
// ---------------------------------------------------------------------------
#define QKV_A(buf)  ((buf) * 34816)
#define QKV_B(buf)  (69632 + (buf) * 49152)
#define QKV_SMEM    167936

__global__ __launch_bounds__(384, 1) void qkv_kernel(const float* __restrict__ x)
{
    extern __shared__ char qsm[];

    const int m0 = blockIdx.x * 128;
    const int tid  = threadIdx.x;
    const int wid  = tid >> 5;
    const int lane = tid & 31;
    const int g    = lane >> 2;
    const int tg   = lane & 3;
    const int o    = wid >> 2;          // 0..2
    const int wr   = (wid & 3) * 32;    // warp row base within tile

    const float* Ag = x + (size_t)m0 * Cdim;
    const char*  Bg = (const char*)g_Wf;   // [o][16 chunks][16384 B]

    // Stage chunk 0.
    {
        uint32_t au = s2u(qsm) + QKV_A(0), bu = s2u(qsm) + QKV_B(0);
        #pragma unroll
        for (int t = 0; t < 6; t++) {
            int idx = t * 384 + tid;
            if (idx < 2048) {
                int row = idx >> 4, c = idx & 15;
                cpa16(au + row * 272 + c * 16, Ag + (size_t)row * Cdim + c * 4);
            }
        }
        #pragma unroll
        for (int t = 0; t < 8; t++) {
            int idx = t * 384 + tid;
            int oo = idx >> 10, rem = idx & 1023;
            cpa16(bu + oo * 16384 + rem * 16,
                  Bg + ((size_t)oo * 262144) + rem * 16);
        }
        cpa_commit();
    }

    float oc[2][16][4];
    #pragma unroll
    for (int mb = 0; mb < 2; mb++)
        #pragma unroll
        for (int nb = 0; nb < 16; nb++)
            #pragma unroll
            for (int c = 0; c < 4; c++) oc[mb][nb][c] = 0.f;

    #pragma unroll 1
    for (int kc = 0; kc < 16; kc++) {
        cpa_wait0();
        __syncthreads();
        const int cur = kc & 1;
        if (kc + 1 < 16) {
            uint32_t au = s2u(qsm) + QKV_A(cur ^ 1), bu = s2u(qsm) + QKV_B(cur ^ 1);
            const float* Agn = Ag + (kc + 1) * 64;
            const char*  Bgn = Bg + (size_t)(kc + 1) * 16384;
            #pragma unroll
            for (int t = 0; t < 6; t++) {
                int idx = t * 384 + tid;
                if (idx < 2048) {
                    int row = idx >> 4, c = idx & 15;
                    cpa16(au + row * 272 + c * 16, Agn + (size_t)row * Cdim + c * 4);
                }
            }
            #pragma unroll
            for (int t = 0; t < 8; t++) {
                int idx = t * 384 + tid;
                int oo = idx >> 10, rem = idx & 1023;
                cpa16(bu + oo * 16384 + rem * 16,
                      Bgn + ((size_t)oo * 262144) + rem * 16);
            }
            cpa_commit();
        }

        const float* A = (const float*)(qsm + QKV_A(cur));
        const uint2* B = (const uint2*)(qsm + QKV_B(cur) + o * 16384);
        const int r0 = wr + g;
        #pragma unroll
        for (int ks = 0; ks < 4; ks++) {
            const int k = ks * 16 + 2 * tg;
            uint32_t a0[4], a1[4];
            {
                float2 v;
                v = *(const float2*)&A[(r0     ) * 68 + k    ]; a0[0] = h2u(v.x, v.y);
                v = *(const float2*)&A[(r0 +  8) * 68 + k    ]; a0[1] = h2u(v.x, v.y);
                v = *(const float2*)&A[(r0     ) * 68 + k + 8]; a0[2] = h2u(v.x, v.y);
                v = *(const float2*)&A[(r0 +  8) * 68 + k + 8]; a0[3] = h2u(v.x, v.y);
                v = *(const float2*)&A[(r0 + 16) * 68 + k    ]; a1[0] = h2u(v.x, v.y);
                v = *(const float2*)&A[(r0 + 24) * 68 + k    ]; a1[1] = h2u(v.x, v.y);
                v = *(const float2*)&A[(r0 + 16) * 68 + k + 8]; a1[2] = h2u(v.x, v.y);
                v = *(const float2*)&A[(r0 + 24) * 68 + k + 8]; a1[3] = h2u(v.x, v.y);
            }
            #pragma unroll
            for (int nb = 0; nb < 16; nb++) {
                uint2 bb = B[(ks * 16 + nb) * 32 + lane];
                mma_f16(oc[0][nb], a0, bb.x, bb.y);
                mma_f16(oc[1][nb], a1, bb.x, bb.y);
            }
        }
    }

    if (o < 2) {
        __half* outp = (o == 0) ? g_Qh : g_Kh;
        #pragma unroll
        for (int mb = 0; mb < 2; mb++) {
            int r = m0 + wr + mb * 16 + g;
            #pragma unroll
            for (int nb = 0; nb < 16; nb++) {
                int col = nb * 8 + 2 * tg;
                *(uint32_t*)&outp[(size_t)(r    ) * Hdim + col] = h2u(oc[mb][nb][0], oc[mb][nb][1]);
                *(uint32_t*)&outp[(size_t)(r + 8) * Hdim + col] = h2u(oc[mb][nb][2], oc[mb][nb][3]);
            }
        }
        __syncthreads();   // paired with V-warp sync before Vt reuse of A0
    } else {
        // V: bounce through smem (reuse A buffer 0), emit fragment-packed layout.
        __half* Vt = (__half*)qsm;   // [128][136] halves = 34816 B (fits A0)
        #pragma unroll
        for (int mb = 0; mb < 2; mb++) {
            int lr = wr + mb * 16 + g;
            #pragma unroll
            for (int nb = 0; nb < 16; nb++) {
                int col = nb * 8 + 2 * tg;
                *(uint32_t*)&Vt[(lr    ) * 136 + col] = h2u(oc[mb][nb][0], oc[mb][nb][1]);
                *(uint32_t*)&Vt[(lr + 8) * 136 + col] = h2u(oc[mb][nb][2], oc[mb][nb][3]);
            }
        }
        __syncthreads();
    }

    // All 384 threads: repack V from Vt into g_Vf (two 64-row tiles).
    {
        const unsigned short* Vts = (const unsigned short*)qsm;
        #pragma unroll
        for (int q = 0; q < 11; q++) {
            int e = q * 384 + tid;           // 0..4095
            if (e < 4096) {
                int t64 = e >> 11;           // 0..1
                int rem = e & 2047;
                int s   = rem >> 9;          // k16 block 0..3
                int nb  = (rem >> 5) & 15;
                int l   = rem & 31;
                int gg = l >> 2, tt = l & 3;
                int krow = t64 * 64 + s * 16 + 2 * tt;
                int n = nb * 8 + gg;
                uint2 rr;
                rr.x = (uint32_t)Vts[(krow    ) * 136 + n] |
                       ((uint32_t)Vts[(krow + 1) * 136 + n] << 16);
                rr.y = (uint32_t)Vts[(krow + 8) * 136 + n] |
                       ((uint32_t)Vts[(krow + 9) * 136 + n] << 16);
                g_Vf[(size_t)((m0 >> 6) + t64) * 2048 + rem] = rr;
            }
        }
    }
}

// ---------------------------------------------------------------------------
// Kernel 2: causal flash attention, fp16 m16n8k16, split-KV + q-pairing,
// 64-wide kv tiles, ldmatrix K loads, fragment-packed V, exp2-domain softmax.
// grid (32, 8): blockIdx.x = pair*2 + half. Half h takes 64-tiles of parity h.
// block = 128 (4 warps). Smem: K 2x[64][136]h (34816 B) + Vf 2x16384 B = 67584.
// ---------------------------------------------------------------------------
#define ATTN_SMEM 67584
#define K_BUF(i)  ((i) * 17408)
#define V_BUF(i)  (34816 + (i) * 16384)

__global__ __launch_bounds__(128) void attn_kernel()
{
    extern __shared__ char hsm[];
    const uint32_t sbase = s2u(hsm);

    const int p = (int)blockIdx.x >> 1;
    const int h = (int)blockIdx.x & 1;
    const int b = blockIdx.y;
    const int tid  = threadIdx.x;
    const int wid  = tid >> 5;
    const int lane = tid & 31;
    const int g    = lane >> 2;
    const int tg   = lane & 3;
    const int r0q  = wid * 16 + g;

    const __half* Qg = g_Qh + (size_t)b * Tdim * Hdim;
    const __half* Kg = g_Kh + (size_t)b * Tdim * Hdim;
    const uint2*  Vg = g_Vf + (size_t)b * 32 * 2048;   // 32 64-row tiles/batch

    // Per-lane LDSM row offsets for groups j (matrices: nb=2j+(m>>1), half=m&1).
    uint32_t krow_off[4];
    {
        const int m = lane >> 3, r = lane & 7;
        const int half = m & 1;
        #pragma unroll
        for (int j = 0; j < 4; j++) {
            int row = (2 * j + (m >> 1)) * 8 + r;
            krow_off[j] = (uint32_t)(row * 272 + half * 16);
        }
    }

    #pragma unroll 1
    for (int phase = 0; phase < 2; phase++) {
        const int qt = phase == 0 ? p : 31 - p;
        const int m0 = qt * 64;
        const int cnt = (qt >= h) ? ((qt - h) >> 1) + 1 : 0;  // 64-tiles, parity h

        __syncthreads();  // previous phase's smem fully consumed

        // Stage tile 0 (index h).
        if (cnt > 0) {
            const int i0 = h;
            uint32_t ku = sbase + K_BUF(0), vu = sbase + V_BUF(0);
            const __half* Ksrc = Kg + (size_t)(64 * i0) * Hdim;
            const char*   Vsrc = (const char*)(Vg + (size_t)i0 * 2048);
            #pragma unroll
            for (int t = 0; t < 8; t++) {
                int idx = t * 128 + tid;
                int krow = idx >> 4, kcc = idx & 15;
                cpa16(ku + krow * 272 + kcc * 16, Ksrc + (size_t)krow * Hdim + kcc * 8);
                cpa16(vu + idx * 16, Vsrc + idx * 16);
            }
            cpa_commit();
        }

        // Q fragments straight from global.
        uint32_t qf[8][4];
        {
            const __half* Qr0 = Qg + (size_t)(m0 + r0q) * Hdim;
            const __half* Qr1 = Qr0 + 8 * Hdim;
            #pragma unroll
            for (int ks = 0; ks < 8; ks++) {
                const int kcol = ks * 16 + 2 * tg;
                qf[ks][0] = __ldg((const uint32_t*)(Qr0 + kcol    ));
                qf[ks][1] = __ldg((const uint32_t*)(Qr1 + kcol    ));
                qf[ks][2] = __ldg((const uint32_t*)(Qr0 + kcol + 8));
                qf[ks][3] = __ldg((const uint32_t*)(Qr1 + kcol + 8));
            }
        }

        float of[16][4];
        #pragma unroll
        for (int nb = 0; nb < 16; nb++)
            #pragma unroll
            for (int c = 0; c < 4; c++) of[nb][c] = 0.f;
        float mrow0 = -1e30f, mrow1 = -1e30f, lrow0 = 0.f, lrow1 = 0.f;

        #pragma unroll 1
        for (int j = 0; j < cnt; j++) {
            const int cur = j & 1;
            const int i = 2 * j + h;       // 64-wide tile index
            cpa_wait0();
            __syncthreads();

            if (j + 1 < cnt) {
                const int in = 2 * (j + 1) + h;
                uint32_t ku = sbase + K_BUF(cur ^ 1), vu = sbase + V_BUF(cur ^ 1);
                const __half* Ksrc = Kg + (size_t)(64 * in) * Hdim;
                const char*   Vsrc = (const char*)(Vg + (size_t)in * 2048);
                #pragma unroll
                for (int t = 0; t < 8; t++) {
                    int idx = t * 128 + tid;
                    int krow = idx >> 4, kcc = idx & 15;
                    cpa16(ku + krow * 272 + kcc * 16, Ksrc + (size_t)krow * Hdim + kcc * 8);
                    cpa16(vu + idx * 16, Vsrc + idx * 16);
                }
                cpa_commit();
            }

            const uint32_t kbuf = sbase + K_BUF(cur);
            const char* VcB = hsm + V_BUF(cur);
            const int n0 = 64 * i;

            // S = Q . K^T  (16 q-rows x 64 kv per warp) via ldmatrix.x4.
            float sacc[8][4];
            #pragma unroll
            for (int nb = 0; nb < 8; nb++)
                #pragma unroll
                for (int c = 0; c < 4; c++) sacc[nb][c] = 0.f;

            #pragma unroll
            for (int ks = 0; ks < 8; ks++) {
                #pragma unroll
                for (int jj = 0; jj < 4; jj++) {
                    uint32_t b00, b01, b10, b11;
                    ldsm_x4(b00, b01, b10, b11, kbuf + krow_off[jj] + ks * 32);
                    mma_f16(sacc[2 * jj    ], qf[ks], b00, b01);
                    mma_f16(sacc[2 * jj + 1], qf[ks], b10, b11);
                }
            }

            // Causal mask (diagonal tile only; occurs iff qt parity == h).
            if (i == qt) {
                const int row0 = m0 + r0q;
                const int row1 = row0 + 8;
                #pragma unroll
                for (int nb = 0; nb < 8; nb++) {
                    int c0 = n0 + nb * 8 + 2 * tg;
                    if (c0     > row0) sacc[nb][0] = -1e30f;
                    if (c0 + 1 > row0) sacc[nb][1] = -1e30f;
                    if (c0     > row1) sacc[nb][2] = -1e30f;
                    if (c0 + 1 > row1) sacc[nb][3] = -1e30f;
                }
            }

            // Online softmax in exp2 domain; P stays in registers.
            float mx0 = -1e30f, mx1 = -1e30f;
            #pragma unroll
            for (int nb = 0; nb < 8; nb++) {
                mx0 = fmaxf(mx0, fmaxf(sacc[nb][0], sacc[nb][1]));
                mx1 = fmaxf(mx1, fmaxf(sacc[nb][2], sacc[nb][3]));
            }
            mx0 = fmaxf(mx0, __shfl_xor_sync(0xffffffffu, mx0, 1));
            mx0 = fmaxf(mx0, __shfl_xor_sync(0xffffffffu, mx0, 2));
            mx1 = fmaxf(mx1, __shfl_xor_sync(0xffffffffu, mx1, 1));
            mx1 = fmaxf(mx1, __shfl_xor_sync(0xffffffffu, mx1, 2));

            float mn0 = fmaxf(mrow0, mx0), mn1 = fmaxf(mrow1, mx1);
            float corr0 = exp2f(mrow0 - mn0), corr1 = exp2f(mrow1 - mn1);
            float rs0 = 0.f, rs1 = 0.f;
            uint32_t ph[8][2];
            #pragma unroll
            for (int nb = 0; nb < 8; nb++) {
                float p00 = exp2f(sacc[nb][0] - mn0);
                float p01 = exp2f(sacc[nb][1] - mn0);
                float p10 = exp2f(sacc[nb][2] - mn1);
                float p11 = exp2f(sacc[nb][3] - mn1);
                rs0 += p00 + p01;
                rs1 += p10 + p11;
                ph[nb][0] = h2u(p00, p01);
                ph[nb][1] = h2u(p10, p11);
            }
            rs0 += __shfl_xor_sync(0xffffffffu, rs0, 1);
            rs0 += __shfl_xor_sync(0xffffffffu, rs0, 2);
            rs1 += __shfl_xor_sync(0xffffffffu, rs1, 1);
            rs1 += __shfl_xor_sync(0xffffffffu, rs1, 2);
            lrow0 = lrow0 * corr0 + rs0;
            lrow1 = lrow1 * corr1 + rs1;
            mrow0 = mn0; mrow1 = mn1;
            #pragma unroll
            for (int nb = 0; nb < 16; nb++) {
                of[nb][0] *= corr0; of[nb][1] *= corr0;
                of[nb][2] *= corr1; of[nb][3] *= corr1;
            }

            // O += P . V  (P in registers; V fragment-packed, k = 64).
            #pragma unroll
            for (int ks2 = 0; ks2 < 4; ks2++) {
                uint32_t pa[4] = { ph[2*ks2][0], ph[2*ks2][1],
                                   ph[2*ks2+1][0], ph[2*ks2+1][1] };
                #pragma unroll
                for (int nb = 0; nb < 16; nb++) {
                    uint2 bb = *(const uint2*)(VcB + (((ks2 * 16 + nb) * 32 + lane) << 3));
                    mma_f16(of[nb], pa, bb.x, bb.y);
                }
            }
        }

        const size_t obase = (size_t)h * BT * Hdim;
        const int grow = b * Tdim + m0 + r0q;
        #pragma unroll
        for (int nb = 0; nb < 16; nb++) {
            float2 lo = {of[nb][0], of[nb][1]};
            float2 hi = {of[nb][2], of[nb][3]};
            *(float2*)(g_Op + obase + (size_t)(grow    ) * Hdim + nb * 8 + 2 * tg) = lo;
            *(float2*)(g_Op + obase + (size_t)(grow + 8) * Hdim + nb * 8 + 2 * tg) = hi;
        }
        if (tg == 0) {
            g_m[h * BT + grow    ] = mrow0;
            g_l[h * BT + grow    ] = lrow0;
            g_m[h * BT + grow + 8] = mrow1;
            g_l[h * BT + grow + 8] = lrow1;
        }
    }
}

// ---------------------------------------------------------------------------
// Kernel 3: combine the two split-KV halves (exp2 domain).
// ---------------------------------------------------------------------------
__global__ __launch_bounds__(256) void combine_kernel(float* __restrict__ out)
{
    const int idx = blockIdx.x * 256 + threadIdx.x;
    const int row = idx >> 5;
    const int c4  = idx & 31;

    const float m0 = g_m[row], m1 = g_m[BT + row];
    const float l0 = g_l[row], l1 = g_l[BT + row];
    const float m  = fmaxf(m0, m1);
    const float c0 = exp2f(m0 - m);
    const float c1 = exp2f(m1 - m);
    const float inv = 1.f / (c0 * l0 + c1 * l1);

    const float4 a = *(const float4*)(g_Op + (size_t)row * Hdim + c4 * 4);
    const float4 bb = *(const float4*)(g_Op + (size_t)BT * Hdim
                                       + (size_t)row * Hdim + c4 * 4);
    float4 r;
    r.x = (c0 * a.x + c1 * bb.x) * inv;
    r.y = (c0 * a.y + c1 * bb.y) * inv;
    r.z = (c0 * a.z + c1 * bb.z) * inv;
    r.w = (c0 * a.w + c1 * bb.w) * inv;
    *(float4*)(out + (size_t)row * Hdim + c4 * 4) = r;
}

// ---------------------------------------------------------------------------
extern "C" void kernel_launch(void* const* d_in, const int* in_sizes, int n_in,
                              void* d_out, int out_size)
{
    const float* x  = (const float*)d_in[0];
    const float* Wq = (const float*)d_in[1];
    const float* Wk = (const float*)d_in[2];
    const float* Wv = (const float*)d_in[3];
    float* out = (float*)d_out;

    wf_kernel<<<384, 256>>>(Wq, Wk, Wv);

    cudaFuncSetAttribute(qkv_kernel,
                         cudaFuncAttributeMaxDynamicSharedMemorySize, QKV_SMEM);
    qkv_kernel<<<BT / 128, 384, QKV_SMEM>>>(x);

    cudaFuncSetAttribute(attn_kernel,
                         cudaFuncAttributeMaxDynamicSharedMemorySize, ATTN_SMEM);
    attn_kernel<<<dim3(32, Bdim), 128, ATTN_SMEM>>>();

    combine_kernel<<<(BT * Hdim / 4) / 256, 256>>>(out);
}